// round 7
// baseline (speedup 1.0000x reference)
#include <cuda_runtime.h>
#include <cstdint>

// ============================================================================
// BCQLinear: y = (x[:, in_reorder] @ dequant(qweight))[:, out_reorder]
// M=128, K=N=4096, WBITS=3, GS=OFI=128.
// compute_100-safe: mma.sync m16n8k8 tf32 (RNA), register-fused 3-bit dequant.
// R7 == R6 resubmit (R6 failed in the bench broker before reaching the GPU):
//     offline bit-plane interleave -> 4-bit codes (3-op dequant in GEMM),
//     2x LDS.128 per kstep, cp.async.cg 16B, MLP-4 permute, MLP-16 reduce.
// ============================================================================

#define M_TOK   128
#define IN_F    4096
#define OUT_F   4096
#define NGRP    32
#define NSPLIT  8            // grid.y; 4 groups per CTA
#define NPLANE  8

// Scratch (static __device__ — no allocations)
__device__ float    g_x_frag[NGRP * 16 * 8 * 32 * 4];    // 2 MB  A fragments
__device__ uint32_t g_qnib[NGRP * 32 * 128 * 16];        // 8 MB  packed 4-bit codes
__device__ float    g_t_part[NPLANE * M_TOK * OUT_F];    // 16 MB K-split partials
__device__ float    g_t_sum[M_TOK * OUT_F];              // 2 MB  reduced sum

__device__ __forceinline__ uint32_t f2tf32(float f) {
    uint32_t u;
    asm("cvt.rna.tf32.f32 %0, %1;" : "=r"(u) : "f"(f));   // RNA: zero-mean error
    return u;
}
__device__ __forceinline__ uint32_t smem_u32(const void* p) {
    uint32_t a;
    asm("{ .reg .u64 t; cvta.to.shared.u64 t, %1; cvt.u32.u64 %0, t; }"
        : "=r"(a) : "l"(p));
    return a;
}
__device__ __forceinline__ void cp_async16(uint32_t saddr, const void* gptr) {
    asm volatile("cp.async.cg.shared.global [%0], [%1], 16;"
                 :: "r"(saddr), "l"(gptr));
}
#define CP_COMMIT() asm volatile("cp.async.commit_group;" ::: "memory")
#define CP_WAIT0()  asm volatile("cp.async.wait_group 0;" ::: "memory")

// spread 8 bits so bit t lands at bit 4t
__device__ __forceinline__ uint32_t spread8(uint32_t x) {
    x = (x | (x << 12)) & 0x000F000Fu;
    x = (x | (x << 6))  & 0x03030303u;
    x = (x | (x << 3))  & 0x11111111u;
    return x;
}

// ---------------------------------------------------------------------------
// Kernel 1: gather x[:, in_reorder], tf32-round, A-fragment layout.
// frag map (m16n8k8.tf32 A): r0:(row,k) r1:(row+8,k) r2:(row,k+4) r3:(row+8,k+4)
// ---------------------------------------------------------------------------
__global__ __launch_bounds__(256)
void prep_x_kernel(const float* __restrict__ x, const int* __restrict__ in_reorder) {
    const int t    = blockIdx.x * 256 + threadIdx.x;     // 131072 threads
    const int lane = t & 31;
    const int mt   = (t >> 5) & 7;
    const int ks   = (t >> 8) & 15;
    const int g    = (t >> 12) & 31;
    const int row  = lane >> 2, kc = lane & 3;
    const int mb   = mt * 16, kb = g * 128 + ks * 8;
    float4 v;
    v.x = x[(mb + row    ) * IN_F + __ldg(&in_reorder[kb + kc    ])];
    v.y = x[(mb + row + 8) * IN_F + __ldg(&in_reorder[kb + kc    ])];
    v.z = x[(mb + row    ) * IN_F + __ldg(&in_reorder[kb + kc + 4])];
    v.w = x[(mb + row + 8) * IN_F + __ldg(&in_reorder[kb + kc + 4])];
    v.x = __uint_as_float(f2tf32(v.x));
    v.y = __uint_as_float(f2tf32(v.y));
    v.z = __uint_as_float(f2tf32(v.z));
    v.w = __uint_as_float(f2tf32(v.w));
    ((float4*)g_x_frag)[t] = v;
}

// ---------------------------------------------------------------------------
// Kernel 2: interleave 3 bit-planes into packed 4-bit codes.
// g_qnib[tile][i][ow] word = 8 nibbles, nibble (o&7) = v(i, o=ow*8+(o&7)).
// ---------------------------------------------------------------------------
__global__ __launch_bounds__(256)
void repack_kernel(const int* __restrict__ qweight, const int* __restrict__ offset) {
    const int t    = blockIdx.x * 256 + threadIdx.x;     // 2097152 threads
    const int ow   = t & 15;
    const int i    = (t >> 4) & 127;
    const int tile = t >> 11;                            // g*32 + nb
    const int* src = qweight + __ldg(&offset[tile]);
    const int j    = ow >> 2;                            // word index o0>>5
    const int sh   = (ow & 3) * 8;                       // bit offset o0&31
    const int base = i * 4 + j;
    const uint32_t b0 = ((uint32_t)__ldg(src + base)        >> sh) & 0xFFu;
    const uint32_t b1 = ((uint32_t)__ldg(src + base + 512)  >> sh) & 0xFFu;
    const uint32_t b2 = ((uint32_t)__ldg(src + base + 1024) >> sh) & 0xFFu;
    g_qnib[t] = spread8(b0) | (spread8(b1) << 1) | (spread8(b2) << 2);
}

// ---------------------------------------------------------------------------
// Kernel 3: fused dequant + tf32 mma.sync GEMM.
// grid (32 out-blocks, 8 K-splits) = 256 CTAs, 256 threads, 2 CTAs/SM.
// warp: mh = wid&1 (m-half), nq = wid>>1 (n-quarter).
// Qsm: double-buffered nibble tile [i 128][ow 16] = 8 KB per buffer.
// ---------------------------------------------------------------------------
__global__ __launch_bounds__(256, 2)
void bcq_gemm_kernel(const float* __restrict__ alpha,
                     const float* __restrict__ beta)
{
    __shared__ uint32_t Qsm[2 * 2048];        // 16 KB
    const int tid  = threadIdx.x;
    const int lane = tid & 31;
    const int wid  = tid >> 5;
    const int nb = blockIdx.x, split = blockIdx.y;
    const int mh = wid & 1;
    const int nq = wid >> 1;
    const uint32_t qsm_base = smem_u32(Qsm) + tid * 16;
    const int shv = (lane >> 2) * 4;          // nibble shift (uniform per thread)

    float acc[4][4][4];
    #pragma unroll
    for (int a = 0; a < 4; a++)
        #pragma unroll
        for (int b = 0; b < 4; b++)
            #pragma unroll
            for (int c = 0; c < 4; c++) acc[a][b][c] = 0.f;

    // prologue: async-copy group 0's nibble tile into buffer 0
    {
        const uint32_t* src = g_qnib + (size_t)((split * 4) * 32 + nb) * 2048 + tid * 4;
        cp_async16(qsm_base,        src);
        cp_async16(qsm_base + 4096, src + 1024);
        CP_COMMIT();
    }

    for (int gi = 0; gi < 4; gi++) {
        const int g = split * 4 + gi;

        // alpha/beta LDGs issued before the cp wait (latency overlap)
        float c1[4], c0[4];
        #pragma unroll
        for (int nt = 0; nt < 4; nt++) {
            const int o = nq * 32 + nt * 8 + (lane >> 2);
            const float a = __ldg(&alpha[g * OUT_F + nb * 128 + o]);
            const float b = __ldg(&beta [g * OUT_F + nb * 128 + o]);
            c1[nt] = 2.f * a;                  // w = v*(2a) + (b-7a), q = 2v-7
            c0[nt] = fmaf(-7.f, a, b);
        }

        CP_WAIT0();
        __syncthreads();                       // buf[gi&1] ready; other buf free

        if (gi < 3) {                          // async prefetch next group
            const uint32_t* src = g_qnib + (size_t)((g + 1) * 32 + nb) * 2048 + tid * 4;
            const uint32_t nb_ = qsm_base + ((gi + 1) & 1) * 8192;
            cp_async16(nb_,        src);
            cp_async16(nb_ + 4096, src + 1024);
            CP_COMMIT();
        }

        const uint4* Qh = (const uint4*)(Qsm + (gi & 1) * 2048);
        const float4* Abase =
            ((const float4*)g_x_frag) + (size_t)g * (16 * 8 * 32) + lane;

        #pragma unroll 4
        for (int ks = 0; ks < 16; ks++) {
            // --- A fragments: 4 coalesced LDG.128 (L2-resident) ---
            uint32_t A[4][4];
            #pragma unroll
            for (int mt = 0; mt < 4; mt++) {
                const float4 t = __ldg((const float4*)&Abase[(ks * 8 + mh * 4 + mt) * 32]);
                A[mt][0] = __float_as_uint(t.x);
                A[mt][1] = __float_as_uint(t.y);
                A[mt][2] = __float_as_uint(t.z);
                A[mt][3] = __float_as_uint(t.w);
            }

            // --- nibble rows i0, i0+4: 2 x LDS.128 ---
            const int i0 = ks * 8 + (lane & 3);
            const uint4 rv = Qh[i0 * 4 + nq];
            const uint4 sv = Qh[(i0 + 4) * 4 + nq];
            const uint32_t rr[4] = {rv.x, rv.y, rv.z, rv.w};
            const uint32_t ss[4] = {sv.x, sv.y, sv.z, sv.w};

            // --- dequant: SHF + LOP3 + FADD + FMA + CVT per value ---
            uint32_t B[4][2];
            #pragma unroll
            for (int nt = 0; nt < 4; nt++) {
                const float fl =
                    __uint_as_float(((rr[nt] >> shv) & 0xFu) | 0x4B000000u) - 8388608.f;
                const float fh =
                    __uint_as_float(((ss[nt] >> shv) & 0xFu) | 0x4B000000u) - 8388608.f;
                B[nt][0] = f2tf32(fmaf(fl, c1[nt], c0[nt]));
                B[nt][1] = f2tf32(fmaf(fh, c1[nt], c0[nt]));
            }

            // --- 16 mma.sync per warp per k-step ---
            #pragma unroll
            for (int mt = 0; mt < 4; mt++)
                #pragma unroll
                for (int nt = 0; nt < 4; nt++)
                    asm volatile(
                        "mma.sync.aligned.m16n8k8.row.col.f32.tf32.tf32.f32 "
                        "{%0,%1,%2,%3}, {%4,%5,%6,%7}, {%8,%9}, {%0,%1,%2,%3};"
                        : "+f"(acc[mt][nt][0]), "+f"(acc[mt][nt][1]),
                          "+f"(acc[mt][nt][2]), "+f"(acc[mt][nt][3])
                        : "r"(A[mt][0]), "r"(A[mt][1]), "r"(A[mt][2]), "r"(A[mt][3]),
                          "r"(B[nt][0]), "r"(B[nt][1]));
        }
    }

    // --- epilogue: K-split partials, plane = split (deterministic) ---
    float* dst = g_t_part + (size_t)split * (M_TOK * OUT_F);
    #pragma unroll
    for (int mt = 0; mt < 4; mt++) {
        const int row0 = mh * 64 + mt * 16 + (lane >> 2);
        #pragma unroll
        for (int nt = 0; nt < 4; nt++) {
            const int col = nb * 128 + nq * 32 + nt * 8 + (lane & 3) * 2;
            *(float2*)&dst[ row0      * OUT_F + col] =
                make_float2(acc[mt][nt][0], acc[mt][nt][1]);
            *(float2*)&dst[(row0 + 8) * OUT_F + col] =
                make_float2(acc[mt][nt][2], acc[mt][nt][3]);
        }
    }
}

// ---------------------------------------------------------------------------
// Kernel 4: reduce 8 planes, coalesced float4, MLP 16
// ---------------------------------------------------------------------------
__global__ __launch_bounds__(256)
void reduce_kernel() {
    const int i = blockIdx.x * 256 + threadIdx.x;        // 65536 threads x 2
    const float4* p = (const float4*)g_t_part;
    #pragma unroll
    for (int h = 0; h < 2; h++) {
        const int e = i + h * 65536;
        float4 s = p[e];
        #pragma unroll
        for (int pl = 1; pl < NPLANE; pl++) {
            const float4 t = p[pl * 131072 + e];
            s.x += t.x; s.y += t.y; s.z += t.z; s.w += t.w;
        }
        ((float4*)g_t_sum)[e] = s;
    }
}

// ---------------------------------------------------------------------------
// Kernel 5: output permutation — coalesced writes, 4 independent gathers
// ---------------------------------------------------------------------------
__global__ __launch_bounds__(256)
void permute_kernel(const int* __restrict__ out_reorder, float* __restrict__ y) {
    const int t = blockIdx.x * 256 + threadIdx.x;        // 131072
    const int c = t & 4095;
    const int mq = t >> 12;                              // 0..31
    const int n = __ldg(&out_reorder[c]);
    #pragma unroll
    for (int u = 0; u < 4; u++) {
        const int m = mq * 4 + u;
        y[(size_t)m * OUT_F + c] = g_t_sum[(m << 12) | n];
    }
}

// ---------------------------------------------------------------------------
// Launch
// ---------------------------------------------------------------------------
extern "C" void kernel_launch(void* const* d_in, const int* in_sizes, int n_in,
                              void* d_out, int out_size) {
    const float* x           = (const float*)d_in[0];
    const int*   qweight     = (const int*)  d_in[1];
    const float* alpha       = (const float*)d_in[2];
    const float* beta        = (const float*)d_in[3];
    // d_in[4] = block_bitwidth (uniform 3, unused)
    const int*   offset      = (const int*)  d_in[5];
    const int*   in_reorder  = (const int*)  d_in[6];
    const int*   out_reorder = (const int*)  d_in[7];
    float* y = (float*)d_out;

    prep_x_kernel<<<512, 256>>>(x, in_reorder);
    repack_kernel<<<8192, 256>>>(qweight, offset);
    bcq_gemm_kernel<<<dim3(32, NSPLIT), 256>>>(alpha, beta);
    reduce_kernel<<<256, 256>>>();
    permute_kernel<<<512, 256>>>(out_reorder, y);
}